// round 1
// baseline (speedup 1.0000x reference)
#include <cuda_runtime.h>
#include <math.h>

// ---------------- scratch (no runtime allocation allowed) ----------------
__device__ float g_unorm[4 * 64 * 1024];   // (B, D, H*W)
__device__ float g_delta[4 * 64 * 1024];   // (B, D, H*W)
__device__ float g_Bv[4 * 16 * 1024];      // (B, N, H*W)
__device__ float g_Cv[4 * 16 * 1024];      // (B, N, H*W)

// rotation constants: c = cos(radians(-w)), s = sin(radians(-w)) for
// w in {0,45,90,135,180,225,270,315}. The reference's float64 trig values
// differ from these exact values by <=2e-16, which is absorbed by the
// float32 cast of the final pixel coords (ulp ~1e-6 at magnitude 16).
#define RS 0.7071067811865476
__constant__ double d_CS[8] = { 1.0,  RS, 0.0, -RS, -1.0, -RS, 0.0,  RS };
__constant__ double d_SN[8] = { 0.0, -RS, -1.0, -RS,  0.0,  RS, 1.0,  RS };

// ---------------- kernel 1: group norm ----------------
// grid = 16 (b*4+g), block = 512
__global__ __launch_bounds__(512) void k_gn(const float* __restrict__ u,
                                            const float* __restrict__ gw,
                                            const float* __restrict__ gb) {
    int bg = blockIdx.x;
    int b = bg >> 2, g = bg & 3;
    const float* base = u + ((size_t)b * 64 + g * 16) * 1024;

    float s = 0.f, q = 0.f;
    for (int i = threadIdx.x; i < 16384; i += 512) {
        float v = base[i];
        s += v;
        q += v * v;
    }
    #pragma unroll
    for (int o = 16; o; o >>= 1) {
        s += __shfl_down_sync(0xffffffffu, s, o);
        q += __shfl_down_sync(0xffffffffu, q, o);
    }
    __shared__ float shs[16], shq[16];
    __shared__ float smu, srs;
    int wid = threadIdx.x >> 5, lid = threadIdx.x & 31;
    if (lid == 0) { shs[wid] = s; shq[wid] = q; }
    __syncthreads();
    if (threadIdx.x == 0) {
        float ts = 0.f, tq = 0.f;
        #pragma unroll
        for (int i = 0; i < 16; ++i) { ts += shs[i]; tq += shq[i]; }
        float mu = ts * (1.f / 16384.f);
        float var = tq * (1.f / 16384.f) - mu * mu;
        smu = mu;
        srs = rsqrtf(var + 1e-5f);
    }
    __syncthreads();
    float mu = smu, rs = srs;
    float* outp = g_unorm + ((size_t)b * 64 + g * 16) * 1024;
    for (int i = threadIdx.x; i < 16384; i += 512) {
        int ch = g * 16 + (i >> 10);
        outp[i] = (base[i] - mu) * rs * gw[ch] + gb[ch];
    }
}

// ---------------- kernel 2: fused 3x3 convs (delta / B / C) ----------------
// 96 output "channels" per batch: [0,64) delta, [64,80) B, [80,96) C.
// grid = 4b * 48 ocpairs * 2 rowhalves = 384 blocks, block = 128 (4 warps).
// warp w covers rows [rowhalf*16 + w*4, +4), lane = x. 2 oc per warp, 4-row
// register tile: per din 36 LDG vs 72 FMA -> FMA-bound.
__global__ __launch_bounds__(128) void k_conv(const float* __restrict__ wd,
                                              const float* __restrict__ bdelta,
                                              const float* __restrict__ wB,
                                              const float* __restrict__ wC,
                                              const float* __restrict__ dtb) {
    int bx = blockIdx.x;
    int b = bx / 96;
    int rem = bx % 96;
    int ocg = rem >> 1;
    int rowhalf = rem & 1;
    int warp = threadIdx.x >> 5;
    int x = threadIdx.x & 31;
    int rbase = rowhalf * 16 + warp * 4;
    int oc0 = ocg * 2;

    const float* wbase;
    if (oc0 < 64)       wbase = wd + (size_t)oc0 * 576;
    else if (oc0 < 80)  wbase = wB + (size_t)(oc0 - 64) * 576;
    else                wbase = wC + (size_t)(oc0 - 80) * 576;

    const float* inb = g_unorm + (size_t)b * 65536;

    float acc0[4] = {0.f, 0.f, 0.f, 0.f};
    float acc1[4] = {0.f, 0.f, 0.f, 0.f};

    for (int din = 0; din < 64; ++din) {
        const float* ip = inb + din * 1024;
        float in[6][3];
        #pragma unroll
        for (int j = 0; j < 6; ++j) {
            int ry = rbase - 1 + j;
            bool vy = (unsigned)ry < 32u;
            const float* rp = ip + ry * 32;
            #pragma unroll
            for (int kx = 0; kx < 3; ++kx) {
                int xx = x - 1 + kx;
                bool ok = vy && ((unsigned)xx < 32u);
                in[j][kx] = ok ? __ldg(rp + xx) : 0.f;
            }
        }
        const float* wp0 = wbase + din * 9;
        const float* wp1 = wp0 + 576;
        float wA[9], wBv[9];
        #pragma unroll
        for (int k = 0; k < 9; ++k) { wA[k] = __ldg(wp0 + k); wBv[k] = __ldg(wp1 + k); }
        #pragma unroll
        for (int r = 0; r < 4; ++r) {
            #pragma unroll
            for (int ky = 0; ky < 3; ++ky) {
                #pragma unroll
                for (int kx = 0; kx < 3; ++kx) {
                    float iv = in[r + ky][kx];
                    acc0[r] = fmaf(iv, wA[ky * 3 + kx], acc0[r]);
                    acc1[r] = fmaf(iv, wBv[ky * 3 + kx], acc1[r]);
                }
            }
        }
    }

    float dt = __ldg(dtb);
    // epilogue oc0
    {
        int oc = oc0;
        #pragma unroll
        for (int r = 0; r < 4; ++r) {
            int p = (rbase + r) * 32 + x;
            float a = acc0[r];
            if (oc < 64) {
                float v = a + __ldg(bdelta + oc) + dt;
                float sp = (v > 0.f) ? v + log1pf(__expf(-v)) : log1pf(__expf(v));
                g_delta[((size_t)b * 64 + oc) * 1024 + p] = fminf(fmaxf(sp, 1e-4f), 5.f);
            } else if (oc < 80) {
                g_Bv[((size_t)b * 16 + (oc - 64)) * 1024 + p] = a;
            } else {
                g_Cv[((size_t)b * 16 + (oc - 80)) * 1024 + p] = a;
            }
        }
    }
    // epilogue oc0+1
    {
        int oc = oc0 + 1;
        #pragma unroll
        for (int r = 0; r < 4; ++r) {
            int p = (rbase + r) * 32 + x;
            float a = acc1[r];
            if (oc < 64) {
                float v = a + __ldg(bdelta + oc) + dt;
                float sp = (v > 0.f) ? v + log1pf(__expf(-v)) : log1pf(__expf(v));
                g_delta[((size_t)b * 64 + oc) * 1024 + p] = fminf(fmaxf(sp, 1e-4f), 5.f);
            } else if (oc < 80) {
                g_Bv[((size_t)b * 16 + (oc - 64)) * 1024 + p] = a;
            } else {
                g_Cv[((size_t)b * 16 + (oc - 80)) * 1024 + p] = a;
            }
        }
    }
}

// ---------------- kernel 3: transport + SSM update + einsum ----------------
// grid = 2048 = (b*8+v)*64+d, block = 1024 threads (one pixel each).
__global__ __launch_bounds__(1024) void k_trans(const float* __restrict__ u_t,
                                                const float* __restrict__ s_prev,
                                                const float* __restrict__ logA,
                                                const float* __restrict__ Dp,
                                                float* __restrict__ out) {
    int bx = blockIdx.x;
    int d = bx & 63;
    int v = (bx >> 6) & 7;
    int b = bx >> 9;
    int p = threadIdx.x;
    int h = p >> 5;
    int w = p & 31;

    size_t bd = ((size_t)b * 64 + d) * 1024 + p;
    float delta = g_delta[bd];
    float u = __ldg(u_t + bd);

    float abar[16];
    #pragma unroll
    for (int n = 0; n < 16; ++n) {
        float A = -__expf(__ldg(logA + d * 16 + n));
        abar[n] = __expf(delta * A);
    }

    // sampling coords in double, matching the reference's float64 grid math
    double c = d_CS[v], s = d_SN[v];
    double xs = ((double)w + 0.5) * 0.0625 - 1.0;
    double ys = ((double)h + 0.5) * 0.0625 - 1.0;
    float ix = (float)((c * xs - s * ys + 1.0) * 16.0 - 0.5);
    float iy = (float)((s * xs + c * ys + 1.0) * 16.0 - 0.5);

    float x0 = floorf(ix), y0 = floorf(iy);
    float fx1 = ix - x0, fy1 = iy - y0;
    float fx0 = 1.f - fx1, fy0 = 1.f - fy1;
    int xi0 = (int)x0, yi0 = (int)y0;

    int off[4];
    float wt[4];
    #pragma unroll
    for (int c4 = 0; c4 < 4; ++c4) {
        int dy = c4 >> 1, dx = c4 & 1;
        int yc = yi0 + dy, xc = xi0 + dx;
        bool m = ((unsigned)yc < 32u) && ((unsigned)xc < 32u);
        int yi = min(max(yc, 0), 31);
        int xi = min(max(xc, 0), 31);
        off[c4] = yi * 32 + xi;
        float ww = (dy ? fy1 : fy0) * (dx ? fx1 : fx0);
        wt[c4] = m ? ww : 0.f;
    }

    size_t sb = (((size_t)(b * 8 + v) * 64 + d) * 16) * 1024;
    const float* sp = s_prev + sb;
    float* so = out + 2097152 + sb;              // s_new after y_new block
    const float* bvp = g_Bv + (size_t)b * 16384 + p;
    const float* cvp = g_Cv + (size_t)b * 16384 + p;

    float du = delta * u;
    float y = 0.f;
    #pragma unroll 4
    for (int n = 0; n < 16; ++n) {
        const float* pl = sp + n * 1024;
        float st = wt[0] * __ldg(pl + off[0]) + wt[1] * __ldg(pl + off[1]) +
                   wt[2] * __ldg(pl + off[2]) + wt[3] * __ldg(pl + off[3]);
        float snew = fmaf(abar[n], st, du * __ldg(bvp + n * 1024));
        so[n * 1024 + p] = snew;
        y = fmaf(snew, __ldg(cvp + n * 1024), y);
    }
    out[((size_t)(b * 8 + v) * 64 + d) * 1024 + p] = y + u * __ldg(Dp + d);
}

// ---------------- launch ----------------
extern "C" void kernel_launch(void* const* d_in, const int* in_sizes, int n_in,
                              void* d_out, int out_size) {
    const float* u_t     = (const float*)d_in[0];   // (4,64,32,32)
    const float* s_prev  = (const float*)d_in[1];   // (4,8,64,16,32,32)
    const float* gn_w    = (const float*)d_in[2];   // (64)
    const float* gn_b    = (const float*)d_in[3];   // (64)
    const float* cdw     = (const float*)d_in[4];   // (64,64,3,3)
    const float* cdb     = (const float*)d_in[5];   // (64)
    const float* cBw     = (const float*)d_in[6];   // (16,64,3,3)
    const float* cCw     = (const float*)d_in[7];   // (16,64,3,3)
    const float* logA    = (const float*)d_in[8];   // (64,16)
    const float* Dp      = (const float*)d_in[9];   // (64)
    const float* dtb     = (const float*)d_in[10];  // scalar
    float* out = (float*)d_out;                     // y_new (2097152) ++ s_new (33554432)

    k_gn<<<16, 512>>>(u_t, gn_w, gn_b);
    k_conv<<<384, 128>>>(cdw, cdb, cBw, cCw, dtb);
    k_trans<<<2048, 1024>>>(u_t, s_prev, logA, Dp, out);
}

// round 2
// speedup vs baseline: 1.1017x; 1.1017x over previous
#include <cuda_runtime.h>
#include <math.h>

// ---------------- scratch (no runtime allocation allowed) ----------------
__device__ float g_unorm[4 * 64 * 1024];   // (B, D, H*W)
__device__ float g_delta[4 * 64 * 1024];   // (B, D, H*W)
__device__ float g_Bv[4 * 16 * 1024];      // (B, N, H*W)
__device__ float g_Cv[4 * 16 * 1024];      // (B, N, H*W)
__device__ float g_Aneg[64 * 16];          // -exp(log_A_real)

// rotation constants: c = cos(radians(-w)), s = sin(radians(-w)).
// Exact values; the <=2e-16 difference vs the reference's float64 trig is
// absorbed by the float32 cast of the final pixel coords.
#define RS 0.7071067811865476
__constant__ double d_CS[8] = { 1.0,  RS, 0.0, -RS, -1.0, -RS, 0.0,  RS };
__constant__ double d_SN[8] = { 0.0, -RS, -1.0, -RS,  0.0,  RS, 1.0,  RS };

// ---------------- kernel 1: group norm (+ A precompute) ----------------
// grid = 16 (b*4+g), block = 1024
__global__ __launch_bounds__(1024) void k_gn(const float* __restrict__ u,
                                             const float* __restrict__ gw,
                                             const float* __restrict__ gb,
                                             const float* __restrict__ logA) {
    if (blockIdx.x == 0 && threadIdx.x < 1024) {
        g_Aneg[threadIdx.x] = -expf(logA[threadIdx.x]);
    }
    int bg = blockIdx.x;
    int b = bg >> 2, g = bg & 3;
    const float* base = u + ((size_t)b * 64 + g * 16) * 1024;

    float s = 0.f, q = 0.f;
    for (int i = threadIdx.x; i < 16384; i += 1024) {
        float v = base[i];
        s += v;
        q += v * v;
    }
    #pragma unroll
    for (int o = 16; o; o >>= 1) {
        s += __shfl_down_sync(0xffffffffu, s, o);
        q += __shfl_down_sync(0xffffffffu, q, o);
    }
    __shared__ float shs[32], shq[32];
    __shared__ float smu, srs;
    int wid = threadIdx.x >> 5, lid = threadIdx.x & 31;
    if (lid == 0) { shs[wid] = s; shq[wid] = q; }
    __syncthreads();
    if (threadIdx.x == 0) {
        float ts = 0.f, tq = 0.f;
        #pragma unroll
        for (int i = 0; i < 32; ++i) { ts += shs[i]; tq += shq[i]; }
        float mu = ts * (1.f / 16384.f);
        float var = tq * (1.f / 16384.f) - mu * mu;
        smu = mu;
        srs = rsqrtf(var + 1e-5f);
    }
    __syncthreads();
    float mu = smu, rs = srs;
    float* outp = g_unorm + ((size_t)b * 64 + g * 16) * 1024;
    for (int i = threadIdx.x; i < 16384; i += 1024) {
        int ch = g * 16 + (i >> 10);
        outp[i] = (base[i] - mu) * rs * gw[ch] + gb[ch];
    }
}

// ---------------- kernel 2: fused 3x3 convs (delta / B / C) ----------------
// 96 output "channels" per batch: [0,64) delta, [64,80) B, [80,96) C.
// grid = 4b * 48 ocpairs * 4 rowquarters = 768 blocks, block = 128 (4 warps).
// warp w covers rows quarter*8 + w*2 .. +1, lane = x. 2 oc per warp.
// Weights for the block's oc pair staged in smem (1152 floats).
__global__ __launch_bounds__(128) void k_conv(const float* __restrict__ wd,
                                              const float* __restrict__ bdelta,
                                              const float* __restrict__ wB,
                                              const float* __restrict__ wC,
                                              const float* __restrict__ dtb) {
    int bx = blockIdx.x;
    int b = bx / 192;
    int rem = bx % 192;
    int ocg = rem >> 2;
    int quarter = rem & 3;
    int warp = threadIdx.x >> 5;
    int x = threadIdx.x & 31;
    int rbase = quarter * 8 + warp * 2;
    int oc0 = ocg * 2;

    const float* wbase;
    if (oc0 < 64)       wbase = wd + (size_t)oc0 * 576;
    else if (oc0 < 80)  wbase = wB + (size_t)(oc0 - 64) * 576;
    else                wbase = wC + (size_t)(oc0 - 80) * 576;

    __shared__ float swt[1152];   // [2][576]
    for (int i = threadIdx.x; i < 1152; i += 128) swt[i] = __ldg(wbase + i);
    __syncthreads();

    const float* inb = g_unorm + (size_t)b * 65536;

    float acc0[2] = {0.f, 0.f};
    float acc1[2] = {0.f, 0.f};

    for (int din = 0; din < 64; ++din) {
        const float* ip = inb + din * 1024;
        float in[4][3];
        #pragma unroll
        for (int j = 0; j < 4; ++j) {
            int ry = rbase - 1 + j;
            bool vy = (unsigned)ry < 32u;
            const float* rp = ip + ry * 32;
            #pragma unroll
            for (int kx = 0; kx < 3; ++kx) {
                int xx = x - 1 + kx;
                bool ok = vy && ((unsigned)xx < 32u);
                in[j][kx] = ok ? __ldg(rp + xx) : 0.f;
            }
        }
        const float* wp0 = swt + din * 9;
        const float* wp1 = wp0 + 576;
        #pragma unroll
        for (int r = 0; r < 2; ++r) {
            #pragma unroll
            for (int ky = 0; ky < 3; ++ky) {
                #pragma unroll
                for (int kx = 0; kx < 3; ++kx) {
                    float iv = in[r + ky][kx];
                    acc0[r] = fmaf(iv, wp0[ky * 3 + kx], acc0[r]);
                    acc1[r] = fmaf(iv, wp1[ky * 3 + kx], acc1[r]);
                }
            }
        }
    }

    float dt = __ldg(dtb);
    #pragma unroll
    for (int which = 0; which < 2; ++which) {
        int oc = oc0 + which;
        #pragma unroll
        for (int r = 0; r < 2; ++r) {
            int p = (rbase + r) * 32 + x;
            float a = which ? acc1[r] : acc0[r];
            if (oc < 64) {
                float v = a + __ldg(bdelta + oc) + dt;
                float sp = (v > 0.f) ? v + log1pf(__expf(-v)) : log1pf(__expf(v));
                g_delta[((size_t)b * 64 + oc) * 1024 + p] = fminf(fmaxf(sp, 1e-4f), 5.f);
            } else if (oc < 80) {
                g_Bv[((size_t)b * 16 + (oc - 64)) * 1024 + p] = a;
            } else {
                g_Cv[((size_t)b * 16 + (oc - 80)) * 1024 + p] = a;
            }
        }
    }
}

// ---------------- kernel 3: transport + SSM update + einsum ----------------
// grid = 2048 = (b*8+v)*64+d, block = 1024 threads (one pixel each).
// s_prev planes staged in padded smem (row stride 33) so the transpose /
// diagonal gathers are conflict-free LDS instead of 32-wavefront LDGs.
// Even rotations are exact integer permutations -> single-sample path.
__global__ __launch_bounds__(1024) void k_trans(const float* __restrict__ u_t,
                                                const float* __restrict__ s_prev,
                                                const float* __restrict__ Dp,
                                                float* __restrict__ out) {
    __shared__ float sbuf[2][33 * 32];

    int bx = blockIdx.x;
    int d = bx & 63;
    int v = (bx >> 6) & 7;
    int b = bx >> 9;
    int p = threadIdx.x;
    int h = p >> 5;
    int w = p & 31;
    int srow = h * 33 + w;     // padded smem slot this thread fills

    size_t bd = ((size_t)b * 64 + d) * 1024 + p;
    float delta = g_delta[bd];
    float u = __ldg(u_t + bd);

    float abar[16];
    #pragma unroll
    for (int n = 0; n < 16; ++n) {
        abar[n] = __expf(delta * g_Aneg[d * 16 + n]);
    }

    // sampling coords in double, matching the reference's float64 grid math
    double c = d_CS[v], s = d_SN[v];
    double xs = ((double)w + 0.5) * 0.0625 - 1.0;
    double ys = ((double)h + 0.5) * 0.0625 - 1.0;
    float ix = (float)((c * xs - s * ys + 1.0) * 16.0 - 0.5);
    float iy = (float)((s * xs + c * ys + 1.0) * 16.0 - 0.5);

    float x0 = floorf(ix), y0 = floorf(iy);
    float fx1 = ix - x0, fy1 = iy - y0;
    float fx0 = 1.f - fx1, fy0 = 1.f - fy1;
    int xi0 = (int)x0, yi0 = (int)y0;

    bool cardinal = ((v & 1) == 0);   // exact integer permutation, in-bounds

    int soff[4];
    float wt[4];
    #pragma unroll
    for (int c4 = 0; c4 < 4; ++c4) {
        int dy = c4 >> 1, dx = c4 & 1;
        int yc = yi0 + dy, xc = xi0 + dx;
        bool m = ((unsigned)yc < 32u) && ((unsigned)xc < 32u);
        int yi = min(max(yc, 0), 31);
        int xi = min(max(xc, 0), 31);
        soff[c4] = yi * 33 + xi;                    // padded smem index
        float ww = (dy ? fy1 : fy0) * (dx ? fx1 : fx0);
        wt[c4] = m ? ww : 0.f;
    }

    size_t sb = (((size_t)(b * 8 + v) * 64 + d) * 16) * 1024;
    const float* sp = s_prev + sb;
    float* so = out + 2097152 + sb;              // s_new after y_new block
    const float* bvp = g_Bv + (size_t)b * 16384 + p;
    const float* cvp = g_Cv + (size_t)b * 16384 + p;

    // stage plane 0
    sbuf[0][srow] = __ldg(sp + p);
    __syncthreads();

    float du = delta * u;
    float y = 0.f;
    #pragma unroll
    for (int n = 0; n < 16; ++n) {
        int cur = n & 1;
        float nx = 0.f;
        if (n < 15) nx = __ldg(sp + (n + 1) * 1024 + p);   // prefetch next plane

        const float* pl = sbuf[cur];
        float st;
        if (cardinal) {
            st = pl[soff[0]];
        } else {
            st = wt[0] * pl[soff[0]] + wt[1] * pl[soff[1]] +
                 wt[2] * pl[soff[2]] + wt[3] * pl[soff[3]];
        }
        float snew = fmaf(abar[n], st, du * __ldg(bvp + n * 1024));
        so[n * 1024 + p] = snew;
        y = fmaf(snew, __ldg(cvp + n * 1024), y);

        if (n < 15) sbuf[cur ^ 1][srow] = nx;
        __syncthreads();
    }
    out[((size_t)(b * 8 + v) * 64 + d) * 1024 + p] = y + u * __ldg(Dp + d);
}

// ---------------- launch ----------------
extern "C" void kernel_launch(void* const* d_in, const int* in_sizes, int n_in,
                              void* d_out, int out_size) {
    const float* u_t     = (const float*)d_in[0];   // (4,64,32,32)
    const float* s_prev  = (const float*)d_in[1];   // (4,8,64,16,32,32)
    const float* gn_w    = (const float*)d_in[2];   // (64)
    const float* gn_b    = (const float*)d_in[3];   // (64)
    const float* cdw     = (const float*)d_in[4];   // (64,64,3,3)
    const float* cdb     = (const float*)d_in[5];   // (64)
    const float* cBw     = (const float*)d_in[6];   // (16,64,3,3)
    const float* cCw     = (const float*)d_in[7];   // (16,64,3,3)
    const float* logA    = (const float*)d_in[8];   // (64,16)
    const float* Dp      = (const float*)d_in[9];   // (64)
    const float* dtb     = (const float*)d_in[10];  // scalar
    float* out = (float*)d_out;                     // y_new (2097152) ++ s_new (33554432)

    k_gn<<<16, 1024>>>(u_t, gn_w, gn_b, logA);
    k_conv<<<768, 128>>>(cdw, cdb, cBw, cCw, dtb);
    k_trans<<<2048, 1024>>>(u_t, s_prev, Dp, out);
}

// round 6
// speedup vs baseline: 1.4636x; 1.3285x over previous
#include <cuda_runtime.h>
#include <math.h>

// ---------------- scratch (no runtime allocation allowed) ----------------
__device__ float g_unorm[4 * 64 * 1024];   // (B, D, H*W)
__device__ float g_delta[4 * 64 * 1024];   // (B, D, H*W)
__device__ float g_Bv[4 * 16 * 1024];      // (B, N, H*W)
__device__ float g_Cv[4 * 16 * 1024];      // (B, N, H*W)
__device__ float g_Aneg[64 * 16];          // -exp(log_A_real)
__device__ float g_part[16 * 8 * 2];       // groupnorm partial sums

// rotation constants: c = cos(radians(-w)), s = sin(radians(-w)).
#define RS 0.7071067811865476
__constant__ double d_CS[8] = { 1.0,  RS, 0.0, -RS, -1.0, -RS, 0.0,  RS };
__constant__ double d_SN[8] = { 0.0, -RS, -1.0, -RS,  0.0,  RS, 1.0,  RS };

// ---------------- kernel 1a: groupnorm partial sums (+ A precompute) -------
// grid = 128 = (b*4+g)*8 + eighth, block = 256
__global__ __launch_bounds__(256) void k_gn1(const float* __restrict__ u,
                                             const float* __restrict__ logA) {
    int bg = blockIdx.x >> 3, e = blockIdx.x & 7;
    if (blockIdx.x == 0) {
        for (int i = threadIdx.x; i < 1024; i += 256)
            g_Aneg[i] = -expf(logA[i]);
    }
    const float* base = u + (size_t)bg * 16384 + e * 2048;
    float s = 0.f, q = 0.f;
    for (int i = threadIdx.x; i < 2048; i += 256) {
        float v = base[i];
        s += v; q += v * v;
    }
    #pragma unroll
    for (int o = 16; o; o >>= 1) {
        s += __shfl_down_sync(0xffffffffu, s, o);
        q += __shfl_down_sync(0xffffffffu, q, o);
    }
    __shared__ float shs[8], shq[8];
    int wid = threadIdx.x >> 5, lid = threadIdx.x & 31;
    if (lid == 0) { shs[wid] = s; shq[wid] = q; }
    __syncthreads();
    if (threadIdx.x == 0) {
        float ts = 0.f, tq = 0.f;
        #pragma unroll
        for (int i = 0; i < 8; ++i) { ts += shs[i]; tq += shq[i]; }
        g_part[(bg * 8 + e) * 2 + 0] = ts;
        g_part[(bg * 8 + e) * 2 + 1] = tq;
    }
}

// ---------------- kernel 1b: groupnorm normalize ----------------
// grid = 128 same mapping, block = 256
__global__ __launch_bounds__(256) void k_gn2(const float* __restrict__ u,
                                             const float* __restrict__ gw,
                                             const float* __restrict__ gb) {
    int bg = blockIdx.x >> 3, e = blockIdx.x & 7;
    int b = bg >> 2, g = bg & 3;
    float ts = 0.f, tq = 0.f;
    #pragma unroll
    for (int k = 0; k < 8; ++k) {
        ts += g_part[(bg * 8 + k) * 2 + 0];
        tq += g_part[(bg * 8 + k) * 2 + 1];
    }
    float mu = ts * (1.f / 16384.f);
    float var = tq * (1.f / 16384.f) - mu * mu;
    float rs = rsqrtf(var + 1e-5f);

    const float* base = u + (size_t)bg * 16384;
    float* outp = g_unorm + (size_t)b * 65536 + (size_t)g * 16 * 1024;
    for (int i = threadIdx.x; i < 2048; i += 256) {
        int j = e * 2048 + i;
        int ch = g * 16 + (j >> 10);
        outp[j] = (base[j] - mu) * rs * gw[ch] + gb[ch];
    }
}

// ---------------- kernel 2: fused 3x3 convs (delta / B / C) ----------------
// 96 output "channels" per batch: [0,64) delta, [64,80) B, [80,96) C.
// grid = 4b * 48 ocpairs * 2 halves = 384 blocks, block = 128 (4 warps).
// warp covers 4 rows; x-halo via warp shuffles (W=32 == warp width, edges are
// zero padding). Weights staged in smem.
__global__ __launch_bounds__(128) void k_conv(const float* __restrict__ wd,
                                              const float* __restrict__ bdelta,
                                              const float* __restrict__ wB,
                                              const float* __restrict__ wC,
                                              const float* __restrict__ dtb) {
    int bx = blockIdx.x;
    int b = bx / 96;
    int rem = bx % 96;
    int ocg = rem >> 1;
    int half = rem & 1;
    int warp = threadIdx.x >> 5;
    int x = threadIdx.x & 31;
    int rbase = half * 16 + warp * 4;
    int oc0 = ocg * 2;

    const float* wbase;
    if (oc0 < 64)       wbase = wd + (size_t)oc0 * 576;
    else if (oc0 < 80)  wbase = wB + (size_t)(oc0 - 64) * 576;
    else                wbase = wC + (size_t)(oc0 - 80) * 576;

    __shared__ float swt[1152];   // [2][576]
    for (int i = threadIdx.x; i < 1152; i += 128) swt[i] = __ldg(wbase + i);
    __syncthreads();

    const float* inb = g_unorm + (size_t)b * 65536;

    float acc0[4] = {0.f, 0.f, 0.f, 0.f};
    float acc1[4] = {0.f, 0.f, 0.f, 0.f};

    for (int din = 0; din < 64; ++din) {
        const float* ip = inb + din * 1024;
        float cc[6], ll[6], rr[6];
        #pragma unroll
        for (int j = 0; j < 6; ++j) {
            int ry = rbase - 1 + j;
            cc[j] = ((unsigned)ry < 32u) ? __ldg(ip + ry * 32 + x) : 0.f;
        }
        #pragma unroll
        for (int j = 0; j < 6; ++j) {
            float uu = __shfl_up_sync(0xffffffffu, cc[j], 1);
            float dd = __shfl_down_sync(0xffffffffu, cc[j], 1);
            ll[j] = (x == 0) ? 0.f : uu;
            rr[j] = (x == 31) ? 0.f : dd;
        }
        const float* wp0 = swt + din * 9;
        const float* wp1 = wp0 + 576;
        #pragma unroll
        for (int r = 0; r < 4; ++r) {
            #pragma unroll
            for (int ky = 0; ky < 3; ++ky) {
                int j = r + ky;
                acc0[r] = fmaf(ll[j], wp0[ky * 3 + 0], acc0[r]);
                acc0[r] = fmaf(cc[j], wp0[ky * 3 + 1], acc0[r]);
                acc0[r] = fmaf(rr[j], wp0[ky * 3 + 2], acc0[r]);
                acc1[r] = fmaf(ll[j], wp1[ky * 3 + 0], acc1[r]);
                acc1[r] = fmaf(cc[j], wp1[ky * 3 + 1], acc1[r]);
                acc1[r] = fmaf(rr[j], wp1[ky * 3 + 2], acc1[r]);
            }
        }
    }

    float dt = __ldg(dtb);
    #pragma unroll
    for (int which = 0; which < 2; ++which) {
        int oc = oc0 + which;
        #pragma unroll
        for (int r = 0; r < 4; ++r) {
            int p = (rbase + r) * 32 + x;
            float a = which ? acc1[r] : acc0[r];
            if (oc < 64) {
                float v = a + __ldg(bdelta + oc) + dt;
                float sp = (v > 0.f) ? v + log1pf(__expf(-v)) : log1pf(__expf(v));
                g_delta[((size_t)b * 64 + oc) * 1024 + p] = fminf(fmaxf(sp, 1e-4f), 5.f);
            } else if (oc < 80) {
                g_Bv[((size_t)b * 16 + (oc - 64)) * 1024 + p] = a;
            } else {
                g_Cv[((size_t)b * 16 + (oc - 80)) * 1024 + p] = a;
            }
        }
    }
}

// ---------------- kernel 3: transport + SSM update + einsum ----------------
// grid = 2048 = (b*8+v)*64+d, block = 1024 threads (one pixel each).
// Planes staged 8-at-a-time (MLP=8 LDG batches), 3 barriers total, second
// batch prefetched into registers before first batch's compute.
__global__ __launch_bounds__(1024) void k_trans(const float* __restrict__ u_t,
                                                const float* __restrict__ s_prev,
                                                const float* __restrict__ Dp,
                                                float* __restrict__ out) {
    __shared__ float sbuf[8][33 * 32];

    int bx = blockIdx.x;
    int d = bx & 63;
    int v = (bx >> 6) & 7;
    int b = bx >> 9;
    int p = threadIdx.x;
    int h = p >> 5;
    int w = p & 31;
    int srow = h * 33 + w;

    size_t bd = ((size_t)b * 64 + d) * 1024 + p;
    float delta = g_delta[bd];
    float u = __ldg(u_t + bd);

    // sampling coords in double, matching the reference's float64 grid math
    double c = d_CS[v], s = d_SN[v];
    double xs = ((double)w + 0.5) * 0.0625 - 1.0;
    double ys = ((double)h + 0.5) * 0.0625 - 1.0;
    float ix = (float)((c * xs - s * ys + 1.0) * 16.0 - 0.5);
    float iy = (float)((s * xs + c * ys + 1.0) * 16.0 - 0.5);

    float x0 = floorf(ix), y0 = floorf(iy);
    float fx1 = ix - x0, fy1 = iy - y0;
    float fx0 = 1.f - fx1, fy0 = 1.f - fy1;
    int xi0 = (int)x0, yi0 = (int)y0;

    bool cardinal = ((v & 1) == 0);   // exact integer permutation, in-bounds

    int soff[4];
    float wt[4];
    #pragma unroll
    for (int c4 = 0; c4 < 4; ++c4) {
        int dy = c4 >> 1, dx = c4 & 1;
        int yc = yi0 + dy, xc = xi0 + dx;
        bool m = ((unsigned)yc < 32u) && ((unsigned)xc < 32u);
        int yi = min(max(yc, 0), 31);
        int xi = min(max(xc, 0), 31);
        soff[c4] = yi * 33 + xi;
        float ww = (dy ? fy1 : fy0) * (dx ? fx1 : fx0);
        wt[c4] = m ? ww : 0.f;
    }

    size_t sb = (((size_t)(b * 8 + v) * 64 + d) * 16) * 1024;
    const float* sp = s_prev + sb;
    float* so = out + 2097152 + sb;              // s_new after y_new block
    const float* bvp = g_Bv + (size_t)b * 16384 + p;
    const float* cvp = g_Cv + (size_t)b * 16384 + p;
    const float* anp = g_Aneg + d * 16;

    float du = delta * u;
    float y = 0.f;
    float stage[8];

    // batch-load planes 0-7 (MLP=8)
    #pragma unroll
    for (int n = 0; n < 8; ++n) stage[n] = __ldg(sp + n * 1024 + p);
    #pragma unroll
    for (int n = 0; n < 8; ++n) sbuf[n][srow] = stage[n];
    __syncthreads();

    // prefetch planes 8-15 into registers BEFORE computing the first batch
    #pragma unroll
    for (int n = 0; n < 8; ++n) stage[n] = __ldg(sp + (8 + n) * 1024 + p);

    #pragma unroll
    for (int n = 0; n < 8; ++n) {
        const float* pl = sbuf[n];
        float st = cardinal ? pl[soff[0]]
                            : wt[0] * pl[soff[0]] + wt[1] * pl[soff[1]] +
                              wt[2] * pl[soff[2]] + wt[3] * pl[soff[3]];
        float abar = __expf(delta * __ldg(anp + n));
        float snew = fmaf(abar, st, du * __ldg(bvp + n * 1024));
        so[n * 1024 + p] = snew;
        y = fmaf(snew, __ldg(cvp + n * 1024), y);
    }
    __syncthreads();
    #pragma unroll
    for (int n = 0; n < 8; ++n) sbuf[n][srow] = stage[n];
    __syncthreads();

    #pragma unroll
    for (int n = 0; n < 8; ++n) {
        const float* pl = sbuf[n];
        float st = cardinal ? pl[soff[0]]
                            : wt[0] * pl[soff[0]] + wt[1] * pl[soff[1]] +
                              wt[2] * pl[soff[2]] + wt[3] * pl[soff[3]];
        float abar = __expf(delta * __ldg(anp + 8 + n));
        float snew = fmaf(abar, st, du * __ldg(bvp + (8 + n) * 1024));
        so[(8 + n) * 1024 + p] = snew;
        y = fmaf(snew, __ldg(cvp + (8 + n) * 1024), y);
    }
    out[((size_t)(b * 8 + v) * 64 + d) * 1024 + p] = y + u * __ldg(Dp + d);
}

// ---------------- launch ----------------
extern "C" void kernel_launch(void* const* d_in, const int* in_sizes, int n_in,
                              void* d_out, int out_size) {
    const float* u_t     = (const float*)d_in[0];   // (4,64,32,32)
    const float* s_prev  = (const float*)d_in[1];   // (4,8,64,16,32,32)
    const float* gn_w    = (const float*)d_in[2];   // (64)
    const float* gn_b    = (const float*)d_in[3];   // (64)
    const float* cdw     = (const float*)d_in[4];   // (64,64,3,3)
    const float* cdb     = (const float*)d_in[5];   // (64)
    const float* cBw     = (const float*)d_in[6];   // (16,64,3,3)
    const float* cCw     = (const float*)d_in[7];   // (16,64,3,3)
    const float* logA    = (const float*)d_in[8];   // (64,16)
    const float* Dp      = (const float*)d_in[9];   // (64)
    const float* dtb     = (const float*)d_in[10];  // scalar
    float* out = (float*)d_out;                     // y_new ++ s_new

    k_gn1<<<128, 256>>>(u_t, logA);
    k_gn2<<<128, 256>>>(u_t, gn_w, gn_b);
    k_conv<<<384, 128>>>(cdw, cdb, cBw, cCw, dtb);
    k_trans<<<2048, 1024>>>(u_t, s_prev, Dp, out);
}

// round 7
// speedup vs baseline: 2.2388x; 1.5297x over previous
#include <cuda_runtime.h>
#include <math.h>

// ---------------- scratch (no runtime allocation allowed) ----------------
__device__ float g_delta[4 * 64 * 1024];   // (B, D, H*W)
__device__ float g_Bv[4 * 16 * 1024];      // (B, N, H*W)
__device__ float g_Cv[4 * 16 * 1024];      // (B, N, H*W)
__device__ float g_Aneg[64 * 16];          // -exp(log_A_real)
__device__ float g_part[16 * 8 * 2];       // groupnorm partial sums

// rotation constants: c = cos(radians(-w)), s = sin(radians(-w)).
#define RS 0.7071067811865476
__constant__ double d_CS[8] = { 1.0,  RS, 0.0, -RS, -1.0, -RS, 0.0,  RS };
__constant__ double d_SN[8] = { 0.0, -RS, -1.0, -RS,  0.0,  RS, 1.0,  RS };

// padded smem row stride for the gather tile: 37 mod 32 = 5 so that diagonal
// rotations (bank stride 0.707*(1 +/- 5)) and the transpose (stride 5,
// coprime with 32) are all conflict-free-ish (<=2-way). Stride 33 made
// v=45/225 hit ~2 banks per warp (16-way serialization).
#define SSTR 37

// ---------------- kernel 1: groupnorm partial sums + A precompute ----------
// grid = 128 = (b*4+g)*8 + eighth, block = 256
__global__ __launch_bounds__(256) void k_gn1(const float* __restrict__ u,
                                             const float* __restrict__ logA) {
    int bg = blockIdx.x >> 3, e = blockIdx.x & 7;
    if (blockIdx.x == 0) {
        for (int i = threadIdx.x; i < 1024; i += 256)
            g_Aneg[i] = -expf(logA[i]);
    }
    const float* base = u + (size_t)bg * 16384 + e * 2048;
    float s = 0.f, q = 0.f;
    for (int i = threadIdx.x; i < 2048; i += 256) {
        float v = base[i];
        s += v; q += v * v;
    }
    #pragma unroll
    for (int o = 16; o; o >>= 1) {
        s += __shfl_down_sync(0xffffffffu, s, o);
        q += __shfl_down_sync(0xffffffffu, q, o);
    }
    __shared__ float shs[8], shq[8];
    int wid = threadIdx.x >> 5, lid = threadIdx.x & 31;
    if (lid == 0) { shs[wid] = s; shq[wid] = q; }
    __syncthreads();
    if (threadIdx.x == 0) {
        float ts = 0.f, tq = 0.f;
        #pragma unroll
        for (int i = 0; i < 8; ++i) { ts += shs[i]; tq += shq[i]; }
        g_part[(bg * 8 + e) * 2 + 0] = ts;
        g_part[(bg * 8 + e) * 2 + 1] = tq;
    }
}

// ---------------- kernel 2: fused groupnorm + 3x3 convs (delta / B / C) ----
// Normalization folded in as per-channel affine on the input loads; no
// g_unorm round-trip. 96 output channels: [0,64) delta, [64,80) B, [80,96) C.
// grid = 4b * 48 ocpairs * 4 quarters = 768 blocks, block = 128 (4 warps).
// warp covers 2 rows; x-halo via warp shuffles.
__global__ __launch_bounds__(128) void k_conv(const float* __restrict__ u,
                                              const float* __restrict__ gw,
                                              const float* __restrict__ gb,
                                              const float* __restrict__ wd,
                                              const float* __restrict__ bdelta,
                                              const float* __restrict__ wB,
                                              const float* __restrict__ wC,
                                              const float* __restrict__ dtb) {
    int bx = blockIdx.x;
    int b = bx / 192;
    int rem = bx % 192;
    int ocg = rem >> 2;
    int quarter = rem & 3;
    int warp = threadIdx.x >> 5;
    int x = threadIdx.x & 31;
    int rbase = quarter * 8 + warp * 2;
    int oc0 = ocg * 2;

    const float* wbase;
    if (oc0 < 64)       wbase = wd + (size_t)oc0 * 576;
    else if (oc0 < 80)  wbase = wB + (size_t)(oc0 - 64) * 576;
    else                wbase = wC + (size_t)(oc0 - 80) * 576;

    __shared__ float swt[1152];       // [2][576]
    __shared__ float ssc[64], ssh[64]; // per-channel affine: scale, shift
    for (int i = threadIdx.x; i < 1152; i += 128) swt[i] = __ldg(wbase + i);
    if (threadIdx.x < 64) {
        int ch = threadIdx.x;
        int g = ch >> 4;
        float ts = 0.f, tq = 0.f;
        #pragma unroll
        for (int k = 0; k < 8; ++k) {
            ts += g_part[((b * 4 + g) * 8 + k) * 2 + 0];
            tq += g_part[((b * 4 + g) * 8 + k) * 2 + 1];
        }
        float mu = ts * (1.f / 16384.f);
        float var = tq * (1.f / 16384.f) - mu * mu;
        float rs = rsqrtf(var + 1e-5f);
        float sc = rs * __ldg(gw + ch);
        ssc[ch] = sc;
        ssh[ch] = __ldg(gb + ch) - mu * sc;
    }
    __syncthreads();

    const float* inb = u + (size_t)b * 65536;

    float acc0[2] = {0.f, 0.f};
    float acc1[2] = {0.f, 0.f};

    for (int din = 0; din < 64; ++din) {
        const float* ip = inb + din * 1024;
        float sc = ssc[din], sh = ssh[din];
        float cc[4], ll[4], rr[4];
        #pragma unroll
        for (int j = 0; j < 4; ++j) {
            int ry = rbase - 1 + j;
            cc[j] = ((unsigned)ry < 32u)
                  ? fmaf(__ldg(ip + ry * 32 + x), sc, sh) : 0.f;
        }
        #pragma unroll
        for (int j = 0; j < 4; ++j) {
            float uu = __shfl_up_sync(0xffffffffu, cc[j], 1);
            float dd = __shfl_down_sync(0xffffffffu, cc[j], 1);
            ll[j] = (x == 0) ? 0.f : uu;
            rr[j] = (x == 31) ? 0.f : dd;
        }
        const float* wp0 = swt + din * 9;
        const float* wp1 = wp0 + 576;
        #pragma unroll
        for (int r = 0; r < 2; ++r) {
            #pragma unroll
            for (int ky = 0; ky < 3; ++ky) {
                int j = r + ky;
                acc0[r] = fmaf(ll[j], wp0[ky * 3 + 0], acc0[r]);
                acc0[r] = fmaf(cc[j], wp0[ky * 3 + 1], acc0[r]);
                acc0[r] = fmaf(rr[j], wp0[ky * 3 + 2], acc0[r]);
                acc1[r] = fmaf(ll[j], wp1[ky * 3 + 0], acc1[r]);
                acc1[r] = fmaf(cc[j], wp1[ky * 3 + 1], acc1[r]);
                acc1[r] = fmaf(rr[j], wp1[ky * 3 + 2], acc1[r]);
            }
        }
    }

    float dt = __ldg(dtb);
    #pragma unroll
    for (int which = 0; which < 2; ++which) {
        int oc = oc0 + which;
        #pragma unroll
        for (int r = 0; r < 2; ++r) {
            int p = (rbase + r) * 32 + x;
            float a = which ? acc1[r] : acc0[r];
            if (oc < 64) {
                float v = a + __ldg(bdelta + oc) + dt;
                float sp = (v > 0.f) ? v + log1pf(__expf(-v)) : log1pf(__expf(v));
                g_delta[((size_t)b * 64 + oc) * 1024 + p] = fminf(fmaxf(sp, 1e-4f), 5.f);
            } else if (oc < 80) {
                g_Bv[((size_t)b * 16 + (oc - 64)) * 1024 + p] = a;
            } else {
                g_Cv[((size_t)b * 16 + (oc - 80)) * 1024 + p] = a;
            }
        }
    }
}

// ---------------- kernel 3: transport + SSM update + einsum ----------------
// grid = 2048 = (b*8+v)*64+d, block = 1024 threads (one pixel each).
// Planes staged 8-at-a-time (MLP=8), 3 barriers; smem rows padded to SSTR=37
// so every rotation's gather is (near-)conflict-free.
__global__ __launch_bounds__(1024) void k_trans(const float* __restrict__ u_t,
                                                const float* __restrict__ s_prev,
                                                const float* __restrict__ Dp,
                                                float* __restrict__ out) {
    __shared__ float sbuf[8][SSTR * 32];

    int bx = blockIdx.x;
    int d = bx & 63;
    int v = (bx >> 6) & 7;
    int b = bx >> 9;
    int p = threadIdx.x;
    int h = p >> 5;
    int w = p & 31;
    int srow = h * SSTR + w;

    size_t bd = ((size_t)b * 64 + d) * 1024 + p;
    float delta = g_delta[bd];
    float u = __ldg(u_t + bd);

    // sampling coords in double, matching the reference's float64 grid math
    double c = d_CS[v], s = d_SN[v];
    double xs = ((double)w + 0.5) * 0.0625 - 1.0;
    double ys = ((double)h + 0.5) * 0.0625 - 1.0;
    float ix = (float)((c * xs - s * ys + 1.0) * 16.0 - 0.5);
    float iy = (float)((s * xs + c * ys + 1.0) * 16.0 - 0.5);

    float x0 = floorf(ix), y0 = floorf(iy);
    float fx1 = ix - x0, fy1 = iy - y0;
    float fx0 = 1.f - fx1, fy0 = 1.f - fy1;
    int xi0 = (int)x0, yi0 = (int)y0;

    bool cardinal = ((v & 1) == 0);   // exact integer permutation, in-bounds

    int soff[4];
    float wt[4];
    #pragma unroll
    for (int c4 = 0; c4 < 4; ++c4) {
        int dy = c4 >> 1, dx = c4 & 1;
        int yc = yi0 + dy, xc = xi0 + dx;
        bool m = ((unsigned)yc < 32u) && ((unsigned)xc < 32u);
        int yi = min(max(yc, 0), 31);
        int xi = min(max(xc, 0), 31);
        soff[c4] = yi * SSTR + xi;
        float ww = (dy ? fy1 : fy0) * (dx ? fx1 : fx0);
        wt[c4] = m ? ww : 0.f;
    }

    size_t sb = (((size_t)(b * 8 + v) * 64 + d) * 16) * 1024;
    const float* sp = s_prev + sb;
    float* so = out + 2097152 + sb;              // s_new after y_new block
    const float* bvp = g_Bv + (size_t)b * 16384 + p;
    const float* cvp = g_Cv + (size_t)b * 16384 + p;
    const float* anp = g_Aneg + d * 16;

    float du = delta * u;
    float y = 0.f;
    float stage[8];

    // batch-load planes 0-7 (MLP=8)
    #pragma unroll
    for (int n = 0; n < 8; ++n) stage[n] = __ldg(sp + n * 1024 + p);
    #pragma unroll
    for (int n = 0; n < 8; ++n) sbuf[n][srow] = stage[n];
    __syncthreads();

    // prefetch planes 8-15 into registers BEFORE computing the first batch
    #pragma unroll
    for (int n = 0; n < 8; ++n) stage[n] = __ldg(sp + (8 + n) * 1024 + p);

    #pragma unroll
    for (int n = 0; n < 8; ++n) {
        const float* pl = sbuf[n];
        float st = cardinal ? pl[soff[0]]
                            : wt[0] * pl[soff[0]] + wt[1] * pl[soff[1]] +
                              wt[2] * pl[soff[2]] + wt[3] * pl[soff[3]];
        float abar = __expf(delta * __ldg(anp + n));
        float snew = fmaf(abar, st, du * __ldg(bvp + n * 1024));
        so[n * 1024 + p] = snew;
        y = fmaf(snew, __ldg(cvp + n * 1024), y);
    }
    __syncthreads();
    #pragma unroll
    for (int n = 0; n < 8; ++n) sbuf[n][srow] = stage[n];
    __syncthreads();

    #pragma unroll
    for (int n = 0; n < 8; ++n) {
        const float* pl = sbuf[n];
        float st = cardinal ? pl[soff[0]]
                            : wt[0] * pl[soff[0]] + wt[1] * pl[soff[1]] +
                              wt[2] * pl[soff[2]] + wt[3] * pl[soff[3]];
        float abar = __expf(delta * __ldg(anp + 8 + n));
        float snew = fmaf(abar, st, du * __ldg(bvp + (8 + n) * 1024));
        so[(8 + n) * 1024 + p] = snew;
        y = fmaf(snew, __ldg(cvp + (8 + n) * 1024), y);
    }
    out[((size_t)(b * 8 + v) * 64 + d) * 1024 + p] = y + u * __ldg(Dp + d);
}

// ---------------- launch ----------------
extern "C" void kernel_launch(void* const* d_in, const int* in_sizes, int n_in,
                              void* d_out, int out_size) {
    const float* u_t     = (const float*)d_in[0];   // (4,64,32,32)
    const float* s_prev  = (const float*)d_in[1];   // (4,8,64,16,32,32)
    const float* gn_w    = (const float*)d_in[2];   // (64)
    const float* gn_b    = (const float*)d_in[3];   // (64)
    const float* cdw     = (const float*)d_in[4];   // (64,64,3,3)
    const float* cdb     = (const float*)d_in[5];   // (64)
    const float* cBw     = (const float*)d_in[6];   // (16,64,3,3)
    const float* cCw     = (const float*)d_in[7];   // (16,64,3,3)
    const float* logA    = (const float*)d_in[8];   // (64,16)
    const float* Dp      = (const float*)d_in[9];   // (64)
    const float* dtb     = (const float*)d_in[10];  // scalar
    float* out = (float*)d_out;                     // y_new ++ s_new

    k_gn1<<<128, 256>>>(u_t, logA);
    k_conv<<<768, 128>>>(u_t, gn_w, gn_b, cdw, cdb, cBw, cCw, dtb);
    k_trans<<<2048, 1024>>>(u_t, s_prev, Dp, out);
}

// round 8
// speedup vs baseline: 2.3500x; 1.0496x over previous
#include <cuda_runtime.h>
#include <math.h>

// ---------------- scratch (no runtime allocation allowed) ----------------
__device__ float g_delta[4 * 64 * 1024];    // (B, D, H*W)
__device__ float g_BC[4 * 16 * 1024 * 2];   // (B, N, H*W, {B,C}) interleaved
__device__ float g_Aneg[64 * 16];           // -exp(log_A_real)
__device__ float g_part[16 * 32 * 2];       // groupnorm partial sums

// rotation constants: c = cos(radians(-w)), s = sin(radians(-w)).
#define RS 0.7071067811865476
__constant__ double d_CS[8] = { 1.0,  RS, 0.0, -RS, -1.0, -RS, 0.0,  RS };
__constant__ double d_SN[8] = { 0.0, -RS, -1.0, -RS,  0.0,  RS, 1.0,  RS };

// padded smem row stride: 37 mod 32 = 5 -> transpose (stride 5, coprime) and
// diagonals (stride 0.707*(1 +/- 5)) all <=2-way bank conflicts.
#define SSTR 37
#define PLANE (SSTR * 32)

// ---------------- kernel 1: groupnorm partial sums + A precompute ----------
// grid = 512 = bg*32 + e, block = 128; one float4 per thread.
__global__ __launch_bounds__(128) void k_gn1(const float* __restrict__ u,
                                             const float* __restrict__ logA) {
    int bg = blockIdx.x >> 5, e = blockIdx.x & 31;
    if (blockIdx.x == 0) {
        #pragma unroll
        for (int i = threadIdx.x; i < 1024; i += 128)
            g_Aneg[i] = -expf(logA[i]);
    }
    const float4* base = (const float4*)(u + (size_t)bg * 16384) + e * 128;
    float4 v4 = __ldg(base + threadIdx.x);
    float s = v4.x + v4.y + v4.z + v4.w;
    float q = v4.x * v4.x + v4.y * v4.y + v4.z * v4.z + v4.w * v4.w;
    #pragma unroll
    for (int o = 16; o; o >>= 1) {
        s += __shfl_down_sync(0xffffffffu, s, o);
        q += __shfl_down_sync(0xffffffffu, q, o);
    }
    __shared__ float shs[4], shq[4];
    int wid = threadIdx.x >> 5, lid = threadIdx.x & 31;
    if (lid == 0) { shs[wid] = s; shq[wid] = q; }
    __syncthreads();
    if (threadIdx.x == 0) {
        float ts = shs[0] + shs[1] + shs[2] + shs[3];
        float tq = shq[0] + shq[1] + shq[2] + shq[3];
        g_part[(bg * 32 + e) * 2 + 0] = ts;
        g_part[(bg * 32 + e) * 2 + 1] = tq;
    }
}

// ---------------- kernel 2: fused groupnorm + 3x3 convs (delta / B / C) ----
// grid = 4b * 48 ocpairs * 4 quarters = 768 blocks, block = 128 (4 warps).
__global__ __launch_bounds__(128) void k_conv(const float* __restrict__ u,
                                              const float* __restrict__ gw,
                                              const float* __restrict__ gb,
                                              const float* __restrict__ wd,
                                              const float* __restrict__ bdelta,
                                              const float* __restrict__ wB,
                                              const float* __restrict__ wC,
                                              const float* __restrict__ dtb) {
    int bx = blockIdx.x;
    int b = bx / 192;
    int rem = bx % 192;
    int ocg = rem >> 2;
    int quarter = rem & 3;
    int warp = threadIdx.x >> 5;
    int x = threadIdx.x & 31;
    int rbase = quarter * 8 + warp * 2;
    int oc0 = ocg * 2;

    const float* wbase;
    if (oc0 < 64)       wbase = wd + (size_t)oc0 * 576;
    else if (oc0 < 80)  wbase = wB + (size_t)(oc0 - 64) * 576;
    else                wbase = wC + (size_t)(oc0 - 80) * 576;

    __shared__ float swt[1152];
    __shared__ float ssc[64], ssh[64];
    for (int i = threadIdx.x; i < 1152; i += 128) swt[i] = __ldg(wbase + i);
    if (threadIdx.x < 64) {
        int ch = threadIdx.x;
        int g = ch >> 4;
        float ts = 0.f, tq = 0.f;
        #pragma unroll
        for (int k = 0; k < 32; ++k) {
            ts += g_part[((b * 4 + g) * 32 + k) * 2 + 0];
            tq += g_part[((b * 4 + g) * 32 + k) * 2 + 1];
        }
        float mu = ts * (1.f / 16384.f);
        float var = tq * (1.f / 16384.f) - mu * mu;
        float rs = rsqrtf(var + 1e-5f);
        float sc = rs * __ldg(gw + ch);
        ssc[ch] = sc;
        ssh[ch] = __ldg(gb + ch) - mu * sc;
    }
    __syncthreads();

    const float* inb = u + (size_t)b * 65536;

    float acc0[2] = {0.f, 0.f};
    float acc1[2] = {0.f, 0.f};

    for (int din = 0; din < 64; ++din) {
        const float* ip = inb + din * 1024;
        float sc = ssc[din], sh = ssh[din];
        float cc[4], ll[4], rr[4];
        #pragma unroll
        for (int j = 0; j < 4; ++j) {
            int ry = rbase - 1 + j;
            cc[j] = ((unsigned)ry < 32u)
                  ? fmaf(__ldg(ip + ry * 32 + x), sc, sh) : 0.f;
        }
        #pragma unroll
        for (int j = 0; j < 4; ++j) {
            float uu = __shfl_up_sync(0xffffffffu, cc[j], 1);
            float dd = __shfl_down_sync(0xffffffffu, cc[j], 1);
            ll[j] = (x == 0) ? 0.f : uu;
            rr[j] = (x == 31) ? 0.f : dd;
        }
        const float* wp0 = swt + din * 9;
        const float* wp1 = wp0 + 576;
        #pragma unroll
        for (int r = 0; r < 2; ++r) {
            #pragma unroll
            for (int ky = 0; ky < 3; ++ky) {
                int j = r + ky;
                acc0[r] = fmaf(ll[j], wp0[ky * 3 + 0], acc0[r]);
                acc0[r] = fmaf(cc[j], wp0[ky * 3 + 1], acc0[r]);
                acc0[r] = fmaf(rr[j], wp0[ky * 3 + 2], acc0[r]);
                acc1[r] = fmaf(ll[j], wp1[ky * 3 + 0], acc1[r]);
                acc1[r] = fmaf(cc[j], wp1[ky * 3 + 1], acc1[r]);
                acc1[r] = fmaf(rr[j], wp1[ky * 3 + 2], acc1[r]);
            }
        }
    }

    float dt = __ldg(dtb);
    #pragma unroll
    for (int which = 0; which < 2; ++which) {
        int oc = oc0 + which;
        #pragma unroll
        for (int r = 0; r < 2; ++r) {
            int p = (rbase + r) * 32 + x;
            float a = which ? acc1[r] : acc0[r];
            if (oc < 64) {
                float v = a + __ldg(bdelta + oc) + dt;
                float sp = (v > 0.f) ? v + log1pf(__expf(-v)) : log1pf(__expf(v));
                g_delta[((size_t)b * 64 + oc) * 1024 + p] = fminf(fmaxf(sp, 1e-4f), 5.f);
            } else if (oc < 80) {
                g_BC[(((size_t)b * 16 + (oc - 64)) * 1024 + p) * 2 + 0] = a;
            } else {
                g_BC[(((size_t)b * 16 + (oc - 80)) * 1024 + p) * 2 + 1] = a;
            }
        }
    }
}

// ---------------- kernel 3: transport + SSM update + einsum ----------------
// grid = 2048 = (b*8+v)*64+d, block = 1024 (one pixel each), 2 blocks/SM.
// v in {0,180}: direct streaming (no smem). Other v: cp.async stages all 16
// planes into padded smem (two commit groups), then gathers.
__global__ __launch_bounds__(1024, 2) void k_trans(const float* __restrict__ u_t,
                                                   const float* __restrict__ s_prev,
                                                   const float* __restrict__ Dp,
                                                   float* __restrict__ out) {
    extern __shared__ float sbuf[];   // [16][PLANE]

    int bx = blockIdx.x;
    int d = bx & 63;
    int v = (bx >> 6) & 7;
    int b = bx >> 9;
    int p = threadIdx.x;
    int h = p >> 5;
    int w = p & 31;

    size_t bd = ((size_t)b * 64 + d) * 1024 + p;
    float delta = g_delta[bd];
    float u = __ldg(u_t + bd);
    float du = delta * u;
    const float* anp = g_Aneg + d * 16;
    const float2* bcp = (const float2*)g_BC + (size_t)b * 16384 + p;

    size_t sb = (((size_t)(b * 8 + v) * 64 + d) * 16) * 1024;
    const float* sp = s_prev + sb;
    float* so = out + 2097152 + sb;              // s_new after y_new block
    float y = 0.f;

    if ((v & 3) == 0) {
        // v==0 (identity) or v==4 (180deg: index reversal) — direct path
        int rp = v ? (1023 - p) : p;
        #pragma unroll
        for (int n = 0; n < 16; ++n) {
            float st = __ldg(sp + n * 1024 + rp);
            float2 bc = __ldg(bcp + n * 1024);
            float abar = __expf(delta * __ldg(anp + n));
            float snew = fmaf(abar, st, du * bc.x);
            so[n * 1024 + p] = snew;
            y = fmaf(snew, bc.y, y);
        }
    } else {
        // sampling coords in double, matching the reference's float64 grid
        double c = d_CS[v], s = d_SN[v];
        double xs = ((double)w + 0.5) * 0.0625 - 1.0;
        double ys = ((double)h + 0.5) * 0.0625 - 1.0;
        float ix = (float)((c * xs - s * ys + 1.0) * 16.0 - 0.5);
        float iy = (float)((s * xs + c * ys + 1.0) * 16.0 - 0.5);

        float x0 = floorf(ix), y0 = floorf(iy);
        float fx1 = ix - x0, fy1 = iy - y0;
        float fx0 = 1.f - fx1, fy0 = 1.f - fy1;
        int xi0 = (int)x0, yi0 = (int)y0;

        bool cardinal = ((v & 1) == 0);   // 90/270: exact integer permutation

        int soff[4];
        float wt[4];
        #pragma unroll
        for (int c4 = 0; c4 < 4; ++c4) {
            int dy = c4 >> 1, dx = c4 & 1;
            int yc = yi0 + dy, xc = xi0 + dx;
            bool m = ((unsigned)yc < 32u) && ((unsigned)xc < 32u);
            int yi = min(max(yc, 0), 31);
            int xi = min(max(xc, 0), 31);
            soff[c4] = yi * SSTR + xi;
            float ww = (dy ? fy1 : fy0) * (dx ? fx1 : fx0);
            wt[c4] = m ? ww : 0.f;
        }

        int srow = h * SSTR + w;
        unsigned sa = (unsigned)__cvta_generic_to_shared(sbuf + srow);

        // stage planes 0-7 (group 1) and 8-15 (group 0) via cp.async
        #pragma unroll
        for (int n = 0; n < 8; ++n)
            asm volatile("cp.async.ca.shared.global [%0], [%1], 4;" ::
                         "r"(sa + n * (PLANE * 4)), "l"(sp + n * 1024 + p));
        asm volatile("cp.async.commit_group;");
        #pragma unroll
        for (int n = 8; n < 16; ++n)
            asm volatile("cp.async.ca.shared.global [%0], [%1], 4;" ::
                         "r"(sa + n * (PLANE * 4)), "l"(sp + n * 1024 + p));
        asm volatile("cp.async.commit_group;");

        asm volatile("cp.async.wait_group 1;");
        __syncthreads();
        #pragma unroll
        for (int n = 0; n < 8; ++n) {
            const float* pl = sbuf + n * PLANE;
            float st = cardinal ? pl[soff[0]]
                                : wt[0] * pl[soff[0]] + wt[1] * pl[soff[1]] +
                                  wt[2] * pl[soff[2]] + wt[3] * pl[soff[3]];
            float2 bc = __ldg(bcp + n * 1024);
            float abar = __expf(delta * __ldg(anp + n));
            float snew = fmaf(abar, st, du * bc.x);
            so[n * 1024 + p] = snew;
            y = fmaf(snew, bc.y, y);
        }
        asm volatile("cp.async.wait_group 0;");
        __syncthreads();
        #pragma unroll
        for (int n = 8; n < 16; ++n) {
            const float* pl = sbuf + n * PLANE;
            float st = cardinal ? pl[soff[0]]
                                : wt[0] * pl[soff[0]] + wt[1] * pl[soff[1]] +
                                  wt[2] * pl[soff[2]] + wt[3] * pl[soff[3]];
            float2 bc = __ldg(bcp + n * 1024);
            float abar = __expf(delta * __ldg(anp + n));
            float snew = fmaf(abar, st, du * bc.x);
            so[n * 1024 + p] = snew;
            y = fmaf(snew, bc.y, y);
        }
    }
    out[((size_t)(b * 8 + v) * 64 + d) * 1024 + p] = y + u * __ldg(Dp + d);
}

// ---------------- launch ----------------
extern "C" void kernel_launch(void* const* d_in, const int* in_sizes, int n_in,
                              void* d_out, int out_size) {
    const float* u_t     = (const float*)d_in[0];
    const float* s_prev  = (const float*)d_in[1];
    const float* gn_w    = (const float*)d_in[2];
    const float* gn_b    = (const float*)d_in[3];
    const float* cdw     = (const float*)d_in[4];
    const float* cdb     = (const float*)d_in[5];
    const float* cBw     = (const float*)d_in[6];
    const float* cCw     = (const float*)d_in[7];
    const float* logA    = (const float*)d_in[8];
    const float* Dp      = (const float*)d_in[9];
    const float* dtb     = (const float*)d_in[10];
    float* out = (float*)d_out;                     // y_new ++ s_new

    static int attr_done = 0;
    if (!attr_done) {
        cudaFuncSetAttribute(k_trans, cudaFuncAttributeMaxDynamicSharedMemorySize,
                             16 * PLANE * 4);
        attr_done = 1;
    }

    k_gn1<<<512, 128>>>(u_t, logA);
    k_conv<<<768, 128>>>(u_t, gn_w, gn_b, cdw, cdb, cBw, cCw, dtb);
    k_trans<<<2048, 1024, 16 * PLANE * 4>>>(u_t, s_prev, Dp, out);
}